// round 3
// baseline (speedup 1.0000x reference)
#include <cuda_runtime.h>
#include <cuda_bf16.h>
#include <cfloat>

// Problem constants
#define SQ 256       // sequence length (B=1)
#define HD 2560      // hidden dim
#define NE 10        // experts
#define NV 50257     // vocab

// -------- scratch (static device arrays; no allocation allowed) ----------
__device__ float g_h[SQ * HD];                       // rmsnorm'd hidden (2.6 MB)
__device__ float g_gate[SQ * NE];                    // gate softmax weights
__device__ float g_eh[NE * SQ * HD];                 // expert hidden (26 MB), row r = e*SQ+s
__device__ float g_m[NE * SQ];                       // per-(e,s) row max
__device__ float g_z[NE * SQ];                       // per-(e,s) sumexp
__device__ float g_logits[(size_t)NE * SQ * NV];     // expert logits (515 MB), row r = e*SQ+s

// ------------------------------ RMSNorm ----------------------------------
__global__ void mos_rmsnorm_kernel(const float* __restrict__ x,
                                   const float* __restrict__ scale) {
    const int s = blockIdx.x, t = threadIdx.x;
    const float* row = x + (size_t)s * HD;
    float v[10];
    float ss = 0.f;
#pragma unroll
    for (int i = 0; i < 10; i++) {
        v[i] = row[t + i * 256];
        ss += v[i] * v[i];
    }
    __shared__ float red[8];
#pragma unroll
    for (int o = 16; o; o >>= 1) ss += __shfl_down_sync(0xffffffffu, ss, o);
    if ((t & 31) == 0) red[t >> 5] = ss;
    __syncthreads();
    if (t < 8) {
        float r = red[t];
#pragma unroll
        for (int o = 4; o; o >>= 1) r += __shfl_down_sync(0xffu, r, o);
        if (t == 0) red[0] = r;
    }
    __syncthreads();
    const float inv = rsqrtf(red[0] * (1.0f / HD) + 1e-5f);
#pragma unroll
    for (int i = 0; i < 10; i++) {
        const int j = t + i * 256;
        g_h[(size_t)s * HD + j] = v[i] * inv * scale[j];
    }
}

// --------------------------- gate softmax --------------------------------
__global__ void mos_gate_kernel(const float* __restrict__ gw) {
    const int s = blockIdx.x, t = threadIdx.x;
    __shared__ float hrow[HD];
    __shared__ float wred[8][NE];
    __shared__ float ge[NE];
    for (int j = t; j < HD; j += 256) hrow[j] = g_h[(size_t)s * HD + j];
    __syncthreads();
    float loc[NE];
#pragma unroll
    for (int e = 0; e < NE; e++) loc[e] = 0.f;
    for (int j = t; j < HD; j += 256) {
        const float hv = hrow[j];
#pragma unroll
        for (int e = 0; e < NE; e++) loc[e] += hv * gw[j * NE + e];
    }
#pragma unroll
    for (int e = 0; e < NE; e++) {
        float r = loc[e];
#pragma unroll
        for (int o = 16; o; o >>= 1) r += __shfl_down_sync(0xffffffffu, r, o);
        if ((t & 31) == 0) wred[t >> 5][e] = r;
    }
    __syncthreads();
    if (t < NE) {
        float r = 0.f;
#pragma unroll
        for (int w = 0; w < 8; w++) r += wred[w][t];
        ge[t] = r;
    }
    __syncthreads();
    if (t == 0) {
        float mx = -FLT_MAX;
#pragma unroll
        for (int e = 0; e < NE; e++) mx = fmaxf(mx, ge[e]);
        float sum = 0.f, ex[NE];
#pragma unroll
        for (int e = 0; e < NE; e++) { ex[e] = __expf(ge[e] - mx); sum += ex[e]; }
#pragma unroll
        for (int e = 0; e < NE; e++) g_gate[s * NE + e] = ex[e] / sum;
    }
}

// -------------- expert GEMM: eh[e,s,d] = sum_h h[s,h] * W[e,h,d] ---------
// A (256 x 2560) row-major; B_e (2560 x 2560) row-major; per-e GEMM.
__global__ __launch_bounds__(256, 2) void mos_expert_gemm_kernel(const float* __restrict__ Wt) {
    const int e = blockIdx.z;
    const int bm = blockIdx.y, bn = blockIdx.x;
    const int tid = threadIdx.x;
    __shared__ float As[8][136];
    __shared__ float Bs[8][136];
    const float* A = g_h;
    const float* B = Wt + (size_t)e * HD * HD;

    float acc[8][8];
#pragma unroll
    for (int i = 0; i < 8; i++)
#pragma unroll
        for (int j = 0; j < 8; j++) acc[i][j] = 0.f;

    const int am = tid >> 1, ak = (tid & 1) * 4;     // A tile: 128 rows x 8 k
    const int bk = tid >> 5, bn4 = (tid & 31) * 4;   // B tile: 8 k-rows x 128 n
    const int tr = (tid >> 4) * 8, tc = (tid & 15) * 8;

    for (int k0 = 0; k0 < HD; k0 += 8) {
        __syncthreads();
        const float4 av = *(const float4*)&A[(size_t)(bm * 128 + am) * HD + k0 + ak];
        As[ak + 0][am] = av.x; As[ak + 1][am] = av.y;
        As[ak + 2][am] = av.z; As[ak + 3][am] = av.w;
        const float4 bv = *(const float4*)&B[(size_t)(k0 + bk) * HD + bn * 128 + bn4];
        *(float4*)&Bs[bk][bn4] = bv;
        __syncthreads();
#pragma unroll
        for (int kk = 0; kk < 8; kk++) {
            float a[8], b[8];
#pragma unroll
            for (int i = 0; i < 8; i++) a[i] = As[kk][tr + i];
#pragma unroll
            for (int j = 0; j < 8; j++) b[j] = Bs[kk][tc + j];
#pragma unroll
            for (int i = 0; i < 8; i++)
#pragma unroll
                for (int j = 0; j < 8; j++) acc[i][j] += a[i] * b[j];
        }
    }
    float* C = g_eh + (size_t)e * SQ * HD;
#pragma unroll
    for (int i = 0; i < 8; i++) {
        const int m = bm * 128 + tr + i;
#pragma unroll
        for (int j = 0; j < 8; j++)
            C[(size_t)m * HD + bn * 128 + tc + j] = acc[i][j];
    }
}

// ------- logits GEMM: L[r,v] = sum_d eh[r,d] * emb[v,d]  (C = A·B^T) -----
// A (2560 x 2560) row-major, B (50257 x 2560) row-major (K contiguous both).
__global__ __launch_bounds__(256, 2) void mos_logits_gemm_kernel(const float* __restrict__ emb) {
    const int bm = blockIdx.y, bn = blockIdx.x;
    const int tid = threadIdx.x;
    __shared__ float As[8][136];
    __shared__ float Bs[8][136];

    float acc[8][8];
#pragma unroll
    for (int i = 0; i < 8; i++)
#pragma unroll
        for (int j = 0; j < 8; j++) acc[i][j] = 0.f;

    const int am = tid >> 1, ak = (tid & 1) * 4;     // A: row am, k quad
    const int bnr = tid >> 1, bkq = (tid & 1) * 4;   // B: vocab row bnr, k quad
    const int tr = (tid >> 4) * 8, tc = (tid & 15) * 8;
    const int vload = bn * 128 + bnr;

    for (int k0 = 0; k0 < HD; k0 += 8) {
        __syncthreads();
        const float4 av = *(const float4*)&g_eh[(size_t)(bm * 128 + am) * HD + k0 + ak];
        As[ak + 0][am] = av.x; As[ak + 1][am] = av.y;
        As[ak + 2][am] = av.z; As[ak + 3][am] = av.w;
        float4 bv = make_float4(0.f, 0.f, 0.f, 0.f);
        if (vload < NV) bv = *(const float4*)&emb[(size_t)vload * HD + k0 + bkq];
        Bs[bkq + 0][bnr] = bv.x; Bs[bkq + 1][bnr] = bv.y;
        Bs[bkq + 2][bnr] = bv.z; Bs[bkq + 3][bnr] = bv.w;
        __syncthreads();
#pragma unroll
        for (int kk = 0; kk < 8; kk++) {
            float a[8], b[8];
#pragma unroll
            for (int i = 0; i < 8; i++) a[i] = As[kk][tr + i];
#pragma unroll
            for (int j = 0; j < 8; j++) b[j] = Bs[kk][tc + j];
#pragma unroll
            for (int i = 0; i < 8; i++)
#pragma unroll
                for (int j = 0; j < 8; j++) acc[i][j] += a[i] * b[j];
        }
    }
#pragma unroll
    for (int i = 0; i < 8; i++) {
        const int r = bm * 128 + tr + i;
#pragma unroll
        for (int j = 0; j < 8; j++) {
            const int v = bn * 128 + tc + j;
            if (v < NV) g_logits[(size_t)r * NV + v] = acc[i][j];
        }
    }
}

// ----------------- per-(e,s) online max + sumexp over V ------------------
__global__ void mos_softmax_stats_kernel() {
    const int r = blockIdx.x, t = threadIdx.x;
    const float* row = g_logits + (size_t)r * NV;
    float m = -FLT_MAX, s = 0.f;
    for (int v = t; v < NV; v += 256) {
        const float x = row[v];
        if (x > m) { s = s * __expf(m - x) + 1.f; m = x; }
        else       { s += __expf(x - m); }
    }
#pragma unroll
    for (int o = 16; o; o >>= 1) {
        const float m2 = __shfl_down_sync(0xffffffffu, m, o);
        const float s2 = __shfl_down_sync(0xffffffffu, s, o);
        if (m2 > m) { s = s * __expf(m - m2) + s2; m = m2; }
        else        { s += s2 * __expf(m2 - m); }
    }
    __shared__ float sm[8], ssum[8];
    if ((t & 31) == 0) { sm[t >> 5] = m; ssum[t >> 5] = s; }
    __syncthreads();
    if (t == 0) {
        m = sm[0]; s = ssum[0];
#pragma unroll
        for (int w = 1; w < 8; w++) {
            const float m2 = sm[w], s2 = ssum[w];
            if (m2 > m) { s = s * __expf(m - m2) + s2; m = m2; }
            else        { s += s2 * __expf(m2 - m); }
        }
        g_m[r] = m; g_z[r] = s;
    }
}

// ------------- mixture of softmaxes + log, write final output ------------
__global__ void mos_final_kernel(float* __restrict__ out) {
    const int s = blockIdx.y, t = threadIdx.x;
    __shared__ float a[NE], mm[NE];
    if (t < NE) {
        const int r = t * SQ + s;
        a[t] = g_gate[s * NE + t] / g_z[r];
        mm[t] = g_m[r];
    }
    __syncthreads();
    const int v = blockIdx.x * 256 + t;
    if (v < NV) {
        float acc = 0.f;
#pragma unroll
        for (int e = 0; e < NE; e++)
            acc += a[e] * __expf(g_logits[(size_t)(e * SQ + s) * NV + v] - mm[e]);
        out[(size_t)s * NV + v] = __logf(acc + 1e-10f);
    }
}

// ------------------------------ launcher ---------------------------------
extern "C" void kernel_launch(void* const* d_in, const int* in_sizes, int n_in,
                              void* d_out, int out_size) {
    const float* hs    = (const float*)d_in[0];  // (1,256,2560)
    const float* emb   = (const float*)d_in[1];  // (50257,2560)
    const float* scale = (const float*)d_in[2];  // (2560,)
    const float* W     = (const float*)d_in[3];  // (10,2560,2560)
    const float* gw    = (const float*)d_in[4];  // (2560,10)
    float* out = (float*)d_out;                  // (1,256,50257)

    mos_rmsnorm_kernel<<<SQ, 256>>>(hs, scale);
    mos_gate_kernel<<<SQ, 256>>>(gw);
    mos_expert_gemm_kernel<<<dim3(HD / 128, SQ / 128, NE), 256>>>(W);
    mos_logits_gemm_kernel<<<dim3((NV + 127) / 128, (NE * SQ) / 128), 256>>>(emb);
    mos_softmax_stats_kernel<<<NE * SQ, 256>>>();
    mos_final_kernel<<<dim3((NV + 255) / 256, SQ), 256>>>(out);
}

// round 8
// speedup vs baseline: 5.1838x; 5.1838x over previous
#include <cuda_runtime.h>
#include <cuda_bf16.h>
#include <cfloat>
#include <cstdint>

// Problem constants
#define SQ 256       // sequence length (B=1)
#define HD 2560      // hidden dim
#define NE 10        // experts
#define NV 50257     // vocab
#define NVP 50432    // vocab padded: 394*128
#define NROW (NE*SQ) // 2560 combined (e,s) rows

// Logits GEMM tiling (mma.sync bf16, Ampere-style — compiles for plain sm_103)
#define BM 128
#define BN 128
#define KT 64                       // K elems per stage (64 bf16 = 128 B rows)
#define NK (HD/KT)                  // 40
#define NSTAGE 3
#define A_STAGE_BYTES (BM*128)      // 16 KB
#define B_STAGE_BYTES (BN*128)      // 16 KB
#define STAGE_BYTES (A_STAGE_BYTES + B_STAGE_BYTES)          // 32 KB
#define SMEM_DYN_TOTAL (NSTAGE*STAGE_BYTES + 1024)           // + align slack

// -------- scratch (static device arrays; no allocation allowed) ----------
__device__ float g_h[SQ * HD];                          // rmsnorm'd hidden
__device__ float g_gate[SQ * NE];                       // gate softmax weights
__device__ __nv_bfloat16 g_eh_bf[NROW * HD];            // expert hidden bf16 (13 MB)
__device__ __nv_bfloat16 g_emb_bf[(size_t)NVP * HD];    // embedding bf16, padded (258 MB)
__device__ float g_p[(size_t)NROW * NVP];               // exp(logits), padded pitch (516 MB)
__device__ float g_z[NROW];                             // per-(e,s) sumexp

// ------------------------------ PTX helpers ------------------------------
#define CP_ASYNC16(dst, src) \
    asm volatile("cp.async.cg.shared.global [%0], [%1], 16;\n" :: "r"(dst), "l"(src))
#define CP_COMMIT() asm volatile("cp.async.commit_group;\n" ::: "memory")
#define CP_WAIT(n)  asm volatile("cp.async.wait_group %0;\n" :: "n"(n) : "memory")

#define LDSM4(r0, r1, r2, r3, addr) \
    asm volatile("ldmatrix.sync.aligned.m8n8.x4.shared.b16 {%0,%1,%2,%3}, [%4];" \
                 : "=r"(r0), "=r"(r1), "=r"(r2), "=r"(r3) : "r"(addr))

#define MMA16816(d, a, b0, b1) \
    asm volatile("mma.sync.aligned.m16n8k16.row.col.f32.bf16.bf16.f32 " \
                 "{%0,%1,%2,%3}, {%4,%5,%6,%7}, {%8,%9}, {%0,%1,%2,%3};" \
                 : "+f"((d)[0]), "+f"((d)[1]), "+f"((d)[2]), "+f"((d)[3]) \
                 : "r"((a)[0]), "r"((a)[1]), "r"((a)[2]), "r"((a)[3]), \
                   "r"(b0), "r"(b1))

__device__ __forceinline__ uint32_t sw128(uint32_t off) {
    return off ^ ((off >> 3) & 0x70);
}

// ------------------------------ RMSNorm ----------------------------------
__global__ void mos_rmsnorm_kernel(const float* __restrict__ x,
                                   const float* __restrict__ scale) {
    const int s = blockIdx.x, t = threadIdx.x;
    const float* row = x + (size_t)s * HD;
    float v[10];
    float ss = 0.f;
#pragma unroll
    for (int i = 0; i < 10; i++) {
        v[i] = row[t + i * 256];
        ss += v[i] * v[i];
    }
    __shared__ float red[8];
#pragma unroll
    for (int o = 16; o; o >>= 1) ss += __shfl_down_sync(0xffffffffu, ss, o);
    if ((t & 31) == 0) red[t >> 5] = ss;
    __syncthreads();
    if (t < 8) {
        float r = red[t];
#pragma unroll
        for (int o = 4; o; o >>= 1) r += __shfl_down_sync(0xffu, r, o);
        if (t == 0) red[0] = r;
    }
    __syncthreads();
    const float inv = rsqrtf(red[0] * (1.0f / HD) + 1e-5f);
#pragma unroll
    for (int i = 0; i < 10; i++) {
        const int j = t + i * 256;
        g_h[(size_t)s * HD + j] = v[i] * inv * scale[j];
    }
}

// --------------------------- gate softmax --------------------------------
__global__ void mos_gate_kernel(const float* __restrict__ gw) {
    const int s = blockIdx.x, t = threadIdx.x;
    __shared__ float hrow[HD];
    __shared__ float wred[8][NE];
    __shared__ float ge[NE];
    for (int j = t; j < HD; j += 256) hrow[j] = g_h[(size_t)s * HD + j];
    __syncthreads();
    float loc[NE];
#pragma unroll
    for (int e = 0; e < NE; e++) loc[e] = 0.f;
    for (int j = t; j < HD; j += 256) {
        const float hv = hrow[j];
#pragma unroll
        for (int e = 0; e < NE; e++) loc[e] += hv * gw[j * NE + e];
    }
#pragma unroll
    for (int e = 0; e < NE; e++) {
        float r = loc[e];
#pragma unroll
        for (int o = 16; o; o >>= 1) r += __shfl_down_sync(0xffffffffu, r, o);
        if ((t & 31) == 0) wred[t >> 5][e] = r;
    }
    __syncthreads();
    if (t < NE) {
        float r = 0.f;
#pragma unroll
        for (int w = 0; w < 8; w++) r += wred[w][t];
        ge[t] = r;
    }
    __syncthreads();
    if (t == 0) {
        float mx = -FLT_MAX;
#pragma unroll
        for (int e = 0; e < NE; e++) mx = fmaxf(mx, ge[e]);
        float sum = 0.f, ex[NE];
#pragma unroll
        for (int e = 0; e < NE; e++) { ex[e] = __expf(ge[e] - mx); sum += ex[e]; }
#pragma unroll
        for (int e = 0; e < NE; e++) g_gate[s * NE + e] = ex[e] / sum;
    }
}

// -------------- expert GEMM: eh[e,s,d] = sum_h h[s,h] * W[e,h,d] ---------
// fp32 SIMT (only 33.6 GF); writes bf16 directly for the tensor-core GEMM.
__global__ __launch_bounds__(256, 2) void mos_expert_gemm_kernel(const float* __restrict__ Wt) {
    const int e = blockIdx.z;
    const int bm = blockIdx.y, bn = blockIdx.x;
    const int tid = threadIdx.x;
    __shared__ float As[8][136];
    __shared__ float Bs[8][136];
    const float* A = g_h;
    const float* B = Wt + (size_t)e * HD * HD;

    float acc[8][8];
#pragma unroll
    for (int i = 0; i < 8; i++)
#pragma unroll
        for (int j = 0; j < 8; j++) acc[i][j] = 0.f;

    const int am = tid >> 1, ak = (tid & 1) * 4;
    const int bk = tid >> 5, bn4 = (tid & 31) * 4;
    const int tr = (tid >> 4) * 8, tc = (tid & 15) * 8;

    for (int k0 = 0; k0 < HD; k0 += 8) {
        __syncthreads();
        const float4 av = *(const float4*)&A[(size_t)(bm * 128 + am) * HD + k0 + ak];
        As[ak + 0][am] = av.x; As[ak + 1][am] = av.y;
        As[ak + 2][am] = av.z; As[ak + 3][am] = av.w;
        const float4 bv = *(const float4*)&B[(size_t)(k0 + bk) * HD + bn * 128 + bn4];
        *(float4*)&Bs[bk][bn4] = bv;
        __syncthreads();
#pragma unroll
        for (int kk = 0; kk < 8; kk++) {
            float a[8], b[8];
#pragma unroll
            for (int i = 0; i < 8; i++) a[i] = As[kk][tr + i];
#pragma unroll
            for (int j = 0; j < 8; j++) b[j] = Bs[kk][tc + j];
#pragma unroll
            for (int i = 0; i < 8; i++)
#pragma unroll
                for (int j = 0; j < 8; j++) acc[i][j] += a[i] * b[j];
        }
    }
#pragma unroll
    for (int i = 0; i < 8; i++) {
        const int m = bm * 128 + tr + i;           // s index within 0..255
        const size_t rowoff = (size_t)(e * SQ + m) * HD;
#pragma unroll
        for (int j = 0; j < 8; j++)
            g_eh_bf[rowoff + bn * 128 + tc + j] = __float2bfloat16(acc[i][j]);
    }
}

// ----------------- embedding fp32 -> bf16 (padded rows zeroed) -----------
__global__ void mos_emb_bf_kernel(const float* __restrict__ emb) {
    const int v = blockIdx.x;     // 0..NVP-1
    const int t = threadIdx.x;    // 256
    __nv_bfloat16* dst = g_emb_bf + (size_t)v * HD;
    if (v < NV) {
        const float4* src = (const float4*)(emb + (size_t)v * HD);
        for (int i = t; i < HD / 4; i += 256) {
            const float4 f = src[i];
            ((__nv_bfloat162*)dst)[2 * i + 0] = __floats2bfloat162_rn(f.x, f.y);
            ((__nv_bfloat162*)dst)[2 * i + 1] = __floats2bfloat162_rn(f.z, f.w);
        }
    } else {
        for (int i = t; i < HD / 4; i += 256)
            ((uint2*)dst)[i] = make_uint2(0u, 0u);
    }
}

// ---------- bf16 mma.sync GEMM: P = exp(eh_bf @ emb_bf^T) ----------------
__device__ __forceinline__ void load_stage(uint32_t sb, int stage, int k0,
                                           int tid, int bm, int bn) {
    const uint32_t abase = sb + stage * STAGE_BYTES;
    const uint32_t bbase = abase + A_STAGE_BYTES;
    const __nv_bfloat16* Ag = g_eh_bf + (size_t)(bm * BM) * HD + k0;
#pragma unroll
    for (int i = 0; i < 4; i++) {                 // 128 rows x 8 chunks / 256 thr
        const int c = tid + i * 256;
        const int row = c >> 3, ch = c & 7;
        const uint32_t dst = abase + sw128(row * 128 + ch * 16);
        CP_ASYNC16(dst, (const char*)(Ag + (size_t)row * HD) + ch * 16);
    }
    const __nv_bfloat16* Bg = g_emb_bf + (size_t)(bn * BN) * HD + k0;
#pragma unroll
    for (int i = 0; i < 4; i++) {
        const int c = tid + i * 256;
        const int row = c >> 3, ch = c & 7;
        const uint32_t dst = bbase + sw128(row * 128 + ch * 16);
        CP_ASYNC16(dst, (const char*)(Bg + (size_t)row * HD) + ch * 16);
    }
}

__global__ __launch_bounds__(256, 2) void mos_logits_mma_kernel() {
    extern __shared__ char smem_raw[];
    uint32_t sbr;
    asm("{ .reg .u64 t; cvta.to.shared.u64 t, %1; cvt.u32.u64 %0, t; }"
        : "=r"(sbr) : "l"(smem_raw));
    const uint32_t sb = (sbr + 1023u) & ~1023u;   // 1024B-align for swizzle

    const int tid = threadIdx.x, wid = tid >> 5, lid = tid & 31;
    const int bm = blockIdx.x, bn = blockIdx.y;   // bm fast -> B-tile L2 reuse
    const int wm = (wid & 3) * 32;                // warp row offset in tile
    const int wn = (wid >> 2) * 64;               // warp col offset in tile

    float d[2][8][4];
#pragma unroll
    for (int mt = 0; mt < 2; mt++)
#pragma unroll
        for (int j = 0; j < 8; j++)
#pragma unroll
            for (int c = 0; c < 4; c++) d[mt][j][c] = 0.f;

    // prologue: stages 0,1
    load_stage(sb, 0, 0, tid, bm, bn);  CP_COMMIT();
    load_stage(sb, 1, KT, tid, bm, bn); CP_COMMIT();

#pragma unroll 1
    for (int k = 0; k < NK; k++) {
        CP_WAIT(1);                    // tile k's group complete
        __syncthreads();               // all warps done computing tile k-1
        if (k + 2 < NK)
            load_stage(sb, (k + 2) % NSTAGE, (k + 2) * KT, tid, bm, bn);
        CP_COMMIT();

        // compute tile k from stage k%NSTAGE
        const uint32_t ab = sb + (k % NSTAGE) * STAGE_BYTES;
        const uint32_t bb = ab + A_STAGE_BYTES;
#pragma unroll
        for (int ks = 0; ks < KT / 16; ks++) {
            uint32_t a[2][4];
#pragma unroll
            for (int mt = 0; mt < 2; mt++) {
                const int row = wm + mt * 16 + (lid & 15);
                const uint32_t addr =
                    ab + sw128(row * 128 + ks * 32 + (lid >> 4) * 16);
                LDSM4(a[mt][0], a[mt][1], a[mt][2], a[mt][3], addr);
            }
            uint32_t b[4][4];
#pragma unroll
            for (int nt = 0; nt < 4; nt++) {
                const int row = wn + nt * 16 + (lid & 15);
                const uint32_t addr =
                    bb + sw128(row * 128 + ks * 32 + (lid >> 4) * 16);
                LDSM4(b[nt][0], b[nt][1], b[nt][2], b[nt][3], addr);
            }
#pragma unroll
            for (int mt = 0; mt < 2; mt++)
#pragma unroll
                for (int nt = 0; nt < 4; nt++) {
                    MMA16816(d[mt][2 * nt + 0], a[mt], b[nt][0], b[nt][2]);
                    MMA16816(d[mt][2 * nt + 1], a[mt], b[nt][1], b[nt][3]);
                }
        }
    }

    // epilogue: exp() in-register, store to padded g_p
    const int r0 = bm * BM + wm;
    const int c0 = bn * BN + wn;
    const int qr = lid >> 2, qc = (lid & 3) * 2;
#pragma unroll
    for (int mt = 0; mt < 2; mt++) {
        const int row = r0 + mt * 16 + qr;
        float* P0 = g_p + (size_t)row * NVP + c0 + qc;
        float* P1 = g_p + (size_t)(row + 8) * NVP + c0 + qc;
#pragma unroll
        for (int j = 0; j < 8; j++) {
            float2 lo, hi;
            lo.x = __expf(d[mt][j][0]); lo.y = __expf(d[mt][j][1]);
            hi.x = __expf(d[mt][j][2]); hi.y = __expf(d[mt][j][3]);
            *(float2*)(P0 + j * 8) = lo;
            *(float2*)(P1 + j * 8) = hi;
        }
    }
}

// ----------------- per-(e,s) row sum of exp(logits) ----------------------
__global__ void mos_rowsum_kernel() {
    const int r = blockIdx.x, t = threadIdx.x;
    const float4* row = (const float4*)(g_p + (size_t)r * NVP);
    float s = 0.f;
    for (int i = t; i < NV / 4; i += 256) {       // covers 50256 elems
        const float4 f = row[i];
        s += (f.x + f.y) + (f.z + f.w);
    }
    if (t == 0) s += g_p[(size_t)r * NVP + (NV - 1)];  // tail elem
#pragma unroll
    for (int o = 16; o; o >>= 1) s += __shfl_down_sync(0xffffffffu, s, o);
    __shared__ float red[8];
    if ((t & 31) == 0) red[t >> 5] = s;
    __syncthreads();
    if (t == 0) {
        float tot = 0.f;
#pragma unroll
        for (int w = 0; w < 8; w++) tot += red[w];
        g_z[r] = tot;
    }
}

// ------------- mixture of softmaxes + log, write final output ------------
__global__ void mos_final_kernel(float* __restrict__ out) {
    const int s = blockIdx.y, t = threadIdx.x;
    __shared__ float a[NE];
    if (t < NE) a[t] = g_gate[s * NE + t] / g_z[t * SQ + s];
    __syncthreads();
    const int v = blockIdx.x * 256 + t;
    if (v < NV) {
        float acc = 0.f;
#pragma unroll
        for (int e = 0; e < NE; e++)
            acc += a[e] * g_p[(size_t)(e * SQ + s) * NVP + v];
        out[(size_t)s * NV + v] = __logf(acc + 1e-10f);
    }
}

// ------------------------------ launcher ---------------------------------
extern "C" void kernel_launch(void* const* d_in, const int* in_sizes, int n_in,
                              void* d_out, int out_size) {
    const float* hs    = (const float*)d_in[0];  // (1,256,2560)
    const float* emb   = (const float*)d_in[1];  // (50257,2560)
    const float* scale = (const float*)d_in[2];  // (2560,)
    const float* W     = (const float*)d_in[3];  // (10,2560,2560)
    const float* gw    = (const float*)d_in[4];  // (2560,10)
    float* out = (float*)d_out;                  // (1,256,50257)

    static int smem_set = 0;
    if (!smem_set) {
        cudaFuncSetAttribute(mos_logits_mma_kernel,
                             cudaFuncAttributeMaxDynamicSharedMemorySize,
                             SMEM_DYN_TOTAL);
        smem_set = 1;
    }

    mos_rmsnorm_kernel<<<SQ, 256>>>(hs, scale);
    mos_gate_kernel<<<SQ, 256>>>(gw);
    mos_emb_bf_kernel<<<NVP, 256>>>(emb);
    mos_expert_gemm_kernel<<<dim3(HD / 128, SQ / 128, NE), 256>>>(W);
    mos_logits_mma_kernel<<<dim3(NROW / BM, NVP / BN), 256, SMEM_DYN_TOTAL>>>();
    mos_rowsum_kernel<<<NROW, 256>>>();
    mos_final_kernel<<<dim3((NV + 255) / 256, SQ), 256>>>(out);
}